// round 5
// baseline (speedup 1.0000x reference)
#include <cuda_runtime.h>
#include <cstdint>

// Fan-model nonlinear mixing:
//   out[b,x] = L + (L^2 - Q)/2
//   L = sum_p E[b,p]   * a[p,x]
//   Q = sum_p E[b,p]^2 * a[p,x]^2
// E: (224, 12)  A: (12, 512*512)  out: (224, 512*512), all fp32.
//
// R5: band-chunked 2D grid. 28 chunks x 8 bands, 256 pixel-groups of
// (128 thr x 8 px) -> 7168 short blocks: near-perfect SM load balance
// (R4 lost ~14% to a ragged 256-block wave), 1.5KB smem E-slice per block,
// A reloads hit L2 (A fully L2-resident). Inner math identical to R4.

#define NPIX (512 * 512)
#define NP   12
#define NB   224
#define BC   8            // bands per block
#define NCHUNK (NB / BC)  // 28

__global__ __launch_bounds__(128, 2) void fm_mix_kernel(
    const float* __restrict__ E,
    const float* __restrict__ A,
    float* __restrict__ out)
{
    const int b0 = blockIdx.y * BC;  // first band of this chunk

    // Per (band,p): {e, e, -e^2, -e^2}; one LDS.128 feeds both packed
    // operands, Q accumulates negated. Only this chunk's slice.
    __shared__ float4 sF[BC * NP];   // 1536 B
    if (threadIdx.x < BC * NP) {
        float e = E[b0 * NP + threadIdx.x];
        sF[threadIdx.x] = make_float4(e, e, -e * e, -e * e);
    }
    __syncthreads();

    uint32_t sbase;
    asm("{ .reg .u64 t; cvta.to.shared.u64 t, %1; cvt.u32.u64 %0, t; }"
        : "=r"(sbase) : "l"(sF));

    const int t = blockIdx.x * blockDim.x + threadIdx.x;  // 8-pixel group id
    // 256 x-blocks * 128 thr * 8 px = NPIX exactly, no bounds check

    // Load a[p] for 8 adjacent pixels (two LDG.128 per p), square once.
    unsigned long long a0[NP], a1[NP], a2[NP], a3[NP];
    unsigned long long s0[NP], s1[NP], s2[NP], s3[NP];
#pragma unroll
    for (int p = 0; p < NP; p++) {
        const ulonglong2* row = (const ulonglong2*)(A + (size_t)p * NPIX);
        const ulonglong2 v0 = row[2 * t];
        const ulonglong2 v1 = row[2 * t + 1];
        a0[p] = v0.x; a1[p] = v0.y; a2[p] = v1.x; a3[p] = v1.y;
        asm("mul.rn.f32x2 %0, %1, %2;" : "=l"(s0[p]) : "l"(v0.x), "l"(v0.x));
        asm("mul.rn.f32x2 %0, %1, %2;" : "=l"(s1[p]) : "l"(v0.y), "l"(v0.y));
        asm("mul.rn.f32x2 %0, %1, %2;" : "=l"(s2[p]) : "l"(v1.x), "l"(v1.x));
        asm("mul.rn.f32x2 %0, %1, %2;" : "=l"(s3[p]) : "l"(v1.y), "l"(v1.y));
    }

    const unsigned long long HALF2 = 0x3F0000003F000000ULL;  // {0.5f, 0.5f}
    // out as u64 (2 px/elem): this thread's 8 px start at 4*t;
    // each band advances NPIX/2 u64 elements.
    unsigned long long* obase =
        (unsigned long long*)out + 4 * (size_t)t + (size_t)b0 * (NPIX / 2);

#pragma unroll 1
    for (int b = 0; b < BC; b++) {
        unsigned long long L0 = 0ULL, Q0 = 0ULL;  // Q accumulates -Q
        unsigned long long L1 = 0ULL, Q1 = 0ULL;
        unsigned long long L2 = 0ULL, Q2 = 0ULL;
        unsigned long long L3 = 0ULL, Q3 = 0ULL;
        const uint32_t addr = sbase + (uint32_t)b * (NP * 16);
#pragma unroll
        for (int p = 0; p < NP; p++) {
            unsigned long long ee, ne2;
            asm("ld.shared.v2.u64 {%0, %1}, [%2];"
                : "=l"(ee), "=l"(ne2) : "r"(addr + p * 16));
            asm("fma.rn.f32x2 %0, %1, %2, %3;" : "=l"(L0) : "l"(a0[p]), "l"(ee),  "l"(L0));
            asm("fma.rn.f32x2 %0, %1, %2, %3;" : "=l"(Q0) : "l"(s0[p]), "l"(ne2), "l"(Q0));
            asm("fma.rn.f32x2 %0, %1, %2, %3;" : "=l"(L1) : "l"(a1[p]), "l"(ee),  "l"(L1));
            asm("fma.rn.f32x2 %0, %1, %2, %3;" : "=l"(Q1) : "l"(s1[p]), "l"(ne2), "l"(Q1));
            asm("fma.rn.f32x2 %0, %1, %2, %3;" : "=l"(L2) : "l"(a2[p]), "l"(ee),  "l"(L2));
            asm("fma.rn.f32x2 %0, %1, %2, %3;" : "=l"(Q2) : "l"(s2[p]), "l"(ne2), "l"(Q2));
            asm("fma.rn.f32x2 %0, %1, %2, %3;" : "=l"(L3) : "l"(a3[p]), "l"(ee),  "l"(L3));
            asm("fma.rn.f32x2 %0, %1, %2, %3;" : "=l"(Q3) : "l"(s3[p]), "l"(ne2), "l"(Q3));
        }
        // res = L + 0.5*(L*L - Q)
        unsigned long long n0, n1, n2, n3, r0, r1, r2, r3;
        asm("fma.rn.f32x2 %0, %1, %1, %2;" : "=l"(n0) : "l"(L0), "l"(Q0));
        asm("fma.rn.f32x2 %0, %1, %1, %2;" : "=l"(n1) : "l"(L1), "l"(Q1));
        asm("fma.rn.f32x2 %0, %1, %1, %2;" : "=l"(n2) : "l"(L2), "l"(Q2));
        asm("fma.rn.f32x2 %0, %1, %1, %2;" : "=l"(n3) : "l"(L3), "l"(Q3));
        asm("fma.rn.f32x2 %0, %1, %2, %3;" : "=l"(r0) : "l"(n0), "l"(HALF2), "l"(L0));
        asm("fma.rn.f32x2 %0, %1, %2, %3;" : "=l"(r1) : "l"(n1), "l"(HALF2), "l"(L1));
        asm("fma.rn.f32x2 %0, %1, %2, %3;" : "=l"(r2) : "l"(n2), "l"(HALF2), "l"(L2));
        asm("fma.rn.f32x2 %0, %1, %2, %3;" : "=l"(r3) : "l"(n3), "l"(HALF2), "l"(L3));

        unsigned long long* ob = obase + (size_t)b * (NPIX / 2);
        asm volatile("st.global.cs.v2.u64 [%0], {%1, %2};"
                     :: "l"(ob), "l"(r0), "l"(r1) : "memory");
        asm volatile("st.global.cs.v2.u64 [%0], {%1, %2};"
                     :: "l"(ob + 2), "l"(r2), "l"(r3) : "memory");
    }
}

extern "C" void kernel_launch(void* const* d_in, const int* in_sizes, int n_in,
                              void* d_out, int out_size)
{
    const float* E = (const float*)d_in[0];
    const float* A = (const float*)d_in[1];
    if (in_sizes[0] > in_sizes[1]) {
        E = (const float*)d_in[1];
        A = (const float*)d_in[0];
    }
    float* out = (float*)d_out;

    dim3 grid((NPIX / 8) / 128, NCHUNK);  // (256, 28)
    fm_mix_kernel<<<grid, 128>>>(E, A, out);
}